// round 17
// baseline (speedup 1.0000x reference)
#include <cuda_runtime.h>

// Problem-shape maxima (compile-time array sizing; runtime uses in_sizes)
#define N1MAX 50000
#define NPMAX 200000
#define H2 32

// ---------------- scratch (static __device__, no allocation) ----------------
__device__ int   g_cnt1 [N1MAX];
__device__ int   g_cnt2f[NPMAX];
__device__ int   g_cnt2b[NPMAX];
__device__ float g_dinv1[N1MAX];
__device__ float g_dinvf[NPMAX];
__device__ float g_dinvb[NPMAX];
__device__ __align__(16) float g_y1  [N1MAX * H2];   // embed: raw xw; after k_scale: xw*dinv1
__device__ __align__(16) float g_out1[N1MAX * H2];   // raw acc: y1[d] + sum y1[src]
__device__ __align__(16) float g_ya  [NPMAX * H2];
__device__ __align__(16) float g_yb  [NPMAX * H2];
__device__ __align__(16) float g_outa[NPMAX * H2];
__device__ __align__(16) float g_outb[NPMAX * H2];

__device__ __forceinline__ void red_add_v4(float* addr, float4 v) {
    asm volatile("red.global.add.v4.f32 [%0], {%1,%2,%3,%4};"
                 :: "l"(addr), "f"(v.x), "f"(v.y), "f"(v.z), "f"(v.w)
                 : "memory");
}

// ---------------- 1. degree counting, 4 edges/thread via int4 --------------
__global__ void k_count(const int* __restrict__ e1, const int* __restrict__ e2,
                        int E1, int E2) {
    int i = blockIdx.x * blockDim.x + threadIdx.x;
    int e0 = i * 4;
    if (e0 < E1) {
        if (e0 + 4 <= E1 && (E1 & 3) == 0) {
            int4 d = *reinterpret_cast<const int4*>(e1 + E1 + e0);
            atomicAdd(&g_cnt1[d.x], 1); atomicAdd(&g_cnt1[d.y], 1);
            atomicAdd(&g_cnt1[d.z], 1); atomicAdd(&g_cnt1[d.w], 1);
        } else {
            for (int k = 0; k < 4 && e0 + k < E1; k++)
                atomicAdd(&g_cnt1[e1[E1 + e0 + k]], 1);
        }
    }
    if (e0 < E2) {
        if (e0 + 4 <= E2 && (E2 & 3) == 0) {
            int4 u = *reinterpret_cast<const int4*>(e2 + e0);
            int4 v = *reinterpret_cast<const int4*>(e2 + E2 + e0);
            atomicAdd(&g_cnt2f[v.x], 1); atomicAdd(&g_cnt2f[v.y], 1);
            atomicAdd(&g_cnt2f[v.z], 1); atomicAdd(&g_cnt2f[v.w], 1);
            atomicAdd(&g_cnt2b[u.x], 1); atomicAdd(&g_cnt2b[u.y], 1);
            atomicAdd(&g_cnt2b[u.z], 1); atomicAdd(&g_cnt2b[u.w], 1);
        } else {
            for (int k = 0; k < 4 && e0 + k < E2; k++) {
                atomicAdd(&g_cnt2f[e2[E2 + e0 + k]], 1);
                atomicAdd(&g_cnt2b[e2[e0 + k]],      1);
            }
        }
    }
}

// ---------------- 2. rsqrt degrees ONCE (deg = count + 1 self-loop) ---------
__global__ void k_dinv(int n1, int np) {
    int i = blockIdx.x * blockDim.x + threadIdx.x;
    if (i < np) {
        g_dinvf[i] = rsqrtf((float)(g_cnt2f[i] + 1));
        g_dinvb[i] = rsqrtf((float)(g_cnt2b[i] + 1));
    }
    if (i < n1) g_dinv1[i] = rsqrtf((float)(g_cnt1[i] + 1));
}

// ---------------- 3. embed GEMM, software-pipelined gather ------------------
// Prefetch chunk ch+1 (A rows + W slab) into registers while computing ch.
__global__ __launch_bounds__(256) void k_embed(
    const int* __restrict__ x, const float* __restrict__ emb,
    const float* __restrict__ W1, int n1)
{
    __shared__ __align__(16) float Ws[64 * 32];       // 8 KB (per-chunk W)
    __shared__ __align__(16) float As[128 * 68];      // 34 KB, row stride 68

    int tid = threadIdx.x;
    int c4 = tid & 7;
    int ty = (tid >> 3) & 7;
    int st = tid >> 6;
    int nodeBase = blockIdx.x * 128;

    float acc[4][4];
    #pragma unroll
    for (int m = 0; m < 4; m++)
        #pragma unroll
        for (int c = 0; c < 4; c++) acc[m][c] = 0.f;

    int lcol = tid & 15;
    int lrow = tid >> 4;

    // node ids for this thread's 8 gather rows (hoisted out of chunk loop)
    int xi[8];
    #pragma unroll
    for (int p = 0; p < 8; p++) {
        int n = nodeBase + lrow + p * 16;
        xi[p] = (n < n1) ? x[n] : 0;
    }

    const float4* emb4 = reinterpret_cast<const float4*>(emb);

    // prologue: stage chunk 0 into registers
    float4 aPre[8];
    float  wPre[8];
    #pragma unroll
    for (int p = 0; p < 8; p++)
        aPre[p] = emb4[(size_t)xi[p] * 64 + lcol];
    #pragma unroll
    for (int i = 0; i < 8; i++)
        wPre[i] = W1[i * 256 + tid];

    for (int ch = 0; ch < 4; ch++) {
        // commit staged chunk to smem
        #pragma unroll
        for (int i = 0; i < 8; i++)
            Ws[i * 256 + tid] = wPre[i];
        #pragma unroll
        for (int p = 0; p < 8; p++)
            *reinterpret_cast<float4*>(&As[(lrow + p * 16) * 68 + lcol * 4]) = aPre[p];
        __syncthreads();

        // prefetch next chunk while computing this one
        if (ch < 3) {
            #pragma unroll
            for (int p = 0; p < 8; p++)
                aPre[p] = emb4[(size_t)xi[p] * 64 + (ch + 1) * 16 + lcol];
            #pragma unroll
            for (int i = 0; i < 8; i++)
                wPre[i] = W1[(ch + 1) * 2048 + i * 256 + tid];
        }

        #pragma unroll
        for (int k4 = 0; k4 < 16; k4++) {
            float4 w0 = *reinterpret_cast<const float4*>(&Ws[(k4 * 4 + 0) * 32 + c4 * 4]);
            float4 w1 = *reinterpret_cast<const float4*>(&Ws[(k4 * 4 + 1) * 32 + c4 * 4]);
            float4 w2 = *reinterpret_cast<const float4*>(&Ws[(k4 * 4 + 2) * 32 + c4 * 4]);
            float4 w3 = *reinterpret_cast<const float4*>(&Ws[(k4 * 4 + 3) * 32 + c4 * 4]);
            #pragma unroll
            for (int m = 0; m < 4; m++) {
                int row = st * 32 + ty + 8 * m;
                float4 a = *reinterpret_cast<const float4*>(&As[row * 68 + k4 * 4]);
                acc[m][0] += a.x * w0.x + a.y * w1.x + a.z * w2.x + a.w * w3.x;
                acc[m][1] += a.x * w0.y + a.y * w1.y + a.z * w2.y + a.w * w3.y;
                acc[m][2] += a.x * w0.z + a.y * w1.z + a.z * w2.z + a.w * w3.z;
                acc[m][3] += a.x * w0.w + a.y * w1.w + a.z * w2.w + a.w * w3.w;
            }
        }
        __syncthreads();
    }

    #pragma unroll
    for (int m = 0; m < 4; m++) {
        int node = nodeBase + st * 32 + ty + 8 * m;
        if (node < n1) {
            *reinterpret_cast<float4*>(&g_y1[node * 32 + c4 * 4]) =
                make_float4(acc[m][0], acc[m][1], acc[m][2], acc[m][3]);
        }
    }
}

// ---------------- 4. scale: y1 = xw*dinv1 (in place), out1 = y1 -------------
__global__ void k_scale(int n1) {
    int i = blockIdx.x * 256 + threadIdx.x;
    int node = i >> 3, t = i & 7;
    if (node >= n1) return;
    float dv = g_dinv1[node];
    float4 v = *reinterpret_cast<const float4*>(&g_y1[node * 32 + t * 4]);
    v.x *= dv; v.y *= dv; v.z *= dv; v.w *= dv;
    *reinterpret_cast<float4*>(&g_y1  [node * 32 + t * 4]) = v;
    *reinterpret_cast<float4*>(&g_out1[node * 32 + t * 4]) = v;   // self-loop init
}

// ---------------- 5. conv1 scatter: 8 edges per 8-thread group, MLP=8 -------
__global__ void k_scatter1(const int* __restrict__ e1, int E1) {
    int tid = blockIdx.x * 256 + threadIdx.x;
    int j = tid >> 3, t = tid & 7;
    int e0 = j * 8;
    if (e0 >= E1) return;

    if (e0 + 8 <= E1 && (E1 & 3) == 0) {
        int4 s0 = *reinterpret_cast<const int4*>(e1 + e0);
        int4 s1 = *reinterpret_cast<const int4*>(e1 + e0 + 4);
        int4 d0 = *reinterpret_cast<const int4*>(e1 + E1 + e0);
        int4 d1 = *reinterpret_cast<const int4*>(e1 + E1 + e0 + 4);
        int s[8] = {s0.x, s0.y, s0.z, s0.w, s1.x, s1.y, s1.z, s1.w};
        int d[8] = {d0.x, d0.y, d0.z, d0.w, d1.x, d1.y, d1.z, d1.w};
        float4 y[8];
        #pragma unroll
        for (int k = 0; k < 8; k++)
            y[k] = *reinterpret_cast<const float4*>(&g_y1[s[k] * 32 + t * 4]);
        #pragma unroll
        for (int k = 0; k < 8; k++)
            red_add_v4(&g_out1[d[k] * 32 + t * 4], y[k]);
    } else {
        for (int k = 0; k < 8; k++) {
            int e = e0 + k;
            if (e < E1) {
                int ss = e1[e], dd = e1[E1 + e];
                float4 y = *reinterpret_cast<const float4*>(&g_y1[ss * 32 + t * 4]);
                red_add_v4(&g_out1[dd * 32 + t * 4], y);
            }
        }
    }
}

// ---------------- 6. pair gather-multiply + fused 32x32 GEMVs ---------------
__global__ __launch_bounds__(256) void k_pair(
    const int* __restrict__ pos,
    const float* __restrict__ W2a, const float* __restrict__ b1v,
    const float* __restrict__ W2b, int np)
{
    __shared__ __align__(16) float Was[1024];
    __shared__ __align__(16) float Wbs[1024];
    int tid = threadIdx.x;
    for (int i = tid; i < 1024; i += 256) { Was[i] = W2a[i]; Wbs[i] = W2b[i]; }
    __syncthreads();

    int g = blockIdx.x * 256 + tid;
    int m = g >> 3, t = g & 7;
    bool ok = (m < np);
    int p0 = 0, p1 = 0;
    if (ok) { p0 = pos[2 * m]; p1 = pos[2 * m + 1]; }

    float dv0 = g_dinv1[p0], dv1 = g_dinv1[p1];
    float4 b14 = *reinterpret_cast<const float4*>(&b1v[t * 4]);
    float4 h0 = *reinterpret_cast<const float4*>(&g_out1[p0 * 32 + t * 4]);
    float4 h1 = *reinterpret_cast<const float4*>(&g_out1[p1 * 32 + t * 4]);
    float4 hp;
    hp.x = fmaxf(h0.x * dv0 + b14.x, 0.f) * fmaxf(h1.x * dv1 + b14.x, 0.f);
    hp.y = fmaxf(h0.y * dv0 + b14.y, 0.f) * fmaxf(h1.y * dv1 + b14.y, 0.f);
    hp.z = fmaxf(h0.z * dv0 + b14.z, 0.f) * fmaxf(h1.z * dv1 + b14.z, 0.f);
    hp.w = fmaxf(h0.w * dv0 + b14.w, 0.f) * fmaxf(h1.w * dv1 + b14.w, 0.f);

    float4 aa = make_float4(0.f, 0.f, 0.f, 0.f);
    float4 ab = make_float4(0.f, 0.f, 0.f, 0.f);
    #pragma unroll
    for (int src = 0; src < 8; src++) {
        float hv[4];
        hv[0] = __shfl_sync(0xffffffffu, hp.x, src, 8);
        hv[1] = __shfl_sync(0xffffffffu, hp.y, src, 8);
        hv[2] = __shfl_sync(0xffffffffu, hp.z, src, 8);
        hv[3] = __shfl_sync(0xffffffffu, hp.w, src, 8);
        #pragma unroll
        for (int kk = 0; kk < 4; kk++) {
            int k = src * 4 + kk;
            float4 wa = *reinterpret_cast<const float4*>(&Was[k * 32 + t * 4]);
            float4 wb = *reinterpret_cast<const float4*>(&Wbs[k * 32 + t * 4]);
            aa.x += hv[kk] * wa.x; aa.y += hv[kk] * wa.y;
            aa.z += hv[kk] * wa.z; aa.w += hv[kk] * wa.w;
            ab.x += hv[kk] * wb.x; ab.y += hv[kk] * wb.y;
            ab.z += hv[kk] * wb.z; ab.w += hv[kk] * wb.w;
        }
    }

    if (ok) {
        float da = g_dinvf[m], db = g_dinvb[m];
        float4 ya = make_float4(aa.x * da, aa.y * da, aa.z * da, aa.w * da);
        float4 yb = make_float4(ab.x * db, ab.y * db, ab.z * db, ab.w * db);
        *reinterpret_cast<float4*>(&g_ya  [m * 32 + t * 4]) = ya;
        *reinterpret_cast<float4*>(&g_yb  [m * 32 + t * 4]) = yb;
        *reinterpret_cast<float4*>(&g_outa[m * 32 + t * 4]) = ya;  // self-loop init
        *reinterpret_cast<float4*>(&g_outb[m * 32 + t * 4]) = yb;  // self-loop init
    }
}

// ---------------- 7. conv2 scatter: 8 edges/group, two phases, MLP=8 --------
__global__ void k_scatter2(const int* __restrict__ e2, int E2) {
    int tid = blockIdx.x * 256 + threadIdx.x;
    int j = tid >> 3, t = tid & 7;
    int e0 = j * 8;
    if (e0 >= E2) return;

    if (e0 + 8 <= E2 && (E2 & 3) == 0) {
        int4 u0 = *reinterpret_cast<const int4*>(e2 + e0);
        int4 u1 = *reinterpret_cast<const int4*>(e2 + e0 + 4);
        int4 v0 = *reinterpret_cast<const int4*>(e2 + E2 + e0);
        int4 v1 = *reinterpret_cast<const int4*>(e2 + E2 + e0 + 4);
        int u[8] = {u0.x, u0.y, u0.z, u0.w, u1.x, u1.y, u1.z, u1.w};
        int v[8] = {v0.x, v0.y, v0.z, v0.w, v1.x, v1.y, v1.z, v1.w};
        float4 y[8];
        #pragma unroll
        for (int k = 0; k < 8; k++)
            y[k] = *reinterpret_cast<const float4*>(&g_ya[u[k] * 32 + t * 4]);
        #pragma unroll
        for (int k = 0; k < 8; k++)
            red_add_v4(&g_outa[v[k] * 32 + t * 4], y[k]);
        #pragma unroll
        for (int k = 0; k < 8; k++)
            y[k] = *reinterpret_cast<const float4*>(&g_yb[v[k] * 32 + t * 4]);
        #pragma unroll
        for (int k = 0; k < 8; k++)
            red_add_v4(&g_outb[u[k] * 32 + t * 4], y[k]);
    } else {
        for (int k = 0; k < 8; k++) {
            int e = e0 + k;
            if (e < E2) {
                int uu = e2[e], vv = e2[E2 + e];
                float4 a = *reinterpret_cast<const float4*>(&g_ya[uu * 32 + t * 4]);
                red_add_v4(&g_outa[vv * 32 + t * 4], a);
                float4 b = *reinterpret_cast<const float4*>(&g_yb[vv * 32 + t * 4]);
                red_add_v4(&g_outb[uu * 32 + t * 4], b);
            }
        }
    }
}

// ---------------- 8. final: deferred conv2 scaling + even*odd + dot Wp ------
__global__ void k_final(const int* __restrict__ idx,
                        const float* __restrict__ b2a, const float* __restrict__ b2b,
                        const float* __restrict__ Wp, const float* __restrict__ bp,
                        float* __restrict__ out, int Q)
{
    int tid = blockIdx.x * 256 + threadIdx.x;
    int q = tid >> 3, t = tid & 7;
    bool ok = (q < Q);
    int i0 = 0, i1 = 0;
    if (ok) { i0 = idx[2 * q]; i1 = idx[2 * q + 1]; }

    float f0 = g_dinvf[i0], g0 = g_dinvb[i0];
    float f1 = g_dinvf[i1], g1 = g_dinvb[i1];
    float4 ba = *reinterpret_cast<const float4*>(&b2a[t * 4]);
    float4 bb = *reinterpret_cast<const float4*>(&b2b[t * 4]);

    float4 a0 = *reinterpret_cast<const float4*>(&g_outa[i0 * 32 + t * 4]);
    float4 c0 = *reinterpret_cast<const float4*>(&g_outb[i0 * 32 + t * 4]);
    float4 a1 = *reinterpret_cast<const float4*>(&g_outa[i1 * 32 + t * 4]);
    float4 c1 = *reinterpret_cast<const float4*>(&g_outb[i1 * 32 + t * 4]);

    float4 h0, h1;
    h0.x = fmaxf(a0.x * f0 + ba.x, 0.f) + fmaxf(c0.x * g0 + bb.x, 0.f);
    h0.y = fmaxf(a0.y * f0 + ba.y, 0.f) + fmaxf(c0.y * g0 + bb.y, 0.f);
    h0.z = fmaxf(a0.z * f0 + ba.z, 0.f) + fmaxf(c0.z * g0 + bb.z, 0.f);
    h0.w = fmaxf(a0.w * f0 + ba.w, 0.f) + fmaxf(c0.w * g0 + bb.w, 0.f);
    h1.x = fmaxf(a1.x * f1 + ba.x, 0.f) + fmaxf(c1.x * g1 + bb.x, 0.f);
    h1.y = fmaxf(a1.y * f1 + ba.y, 0.f) + fmaxf(c1.y * g1 + bb.y, 0.f);
    h1.z = fmaxf(a1.z * f1 + ba.z, 0.f) + fmaxf(c1.z * g1 + bb.z, 0.f);
    h1.w = fmaxf(a1.w * f1 + ba.w, 0.f) + fmaxf(c1.w * g1 + bb.w, 0.f);

    float4 wp4 = *reinterpret_cast<const float4*>(&Wp[t * 4]);
    float s = h0.x * h1.x * wp4.x + h0.y * h1.y * wp4.y
            + h0.z * h1.z * wp4.z + h0.w * h1.w * wp4.w;
    s += __shfl_xor_sync(0xffffffffu, s, 1, 8);
    s += __shfl_xor_sync(0xffffffffu, s, 2, 8);
    s += __shfl_xor_sync(0xffffffffu, s, 4, 8);
    if (ok && t == 0) out[q] = s + __ldg(bp);
}

// ---------------- launch: forked graph (embed || degree pipeline) -----------
extern "C" void kernel_launch(void* const* d_in, const int* in_sizes, int n_in,
                              void* d_out, int out_size) {
    const int*   x    = (const int*)  d_in[0];
    const int*   e1   = (const int*)  d_in[1];
    const int*   pos  = (const int*)  d_in[2];
    const int*   idx  = (const int*)  d_in[3];
    const int*   e2   = (const int*)  d_in[4];
    const float* emb  = (const float*)d_in[5];
    const float* W1   = (const float*)d_in[6];
    const float* b1   = (const float*)d_in[7];
    const float* W2a  = (const float*)d_in[8];
    const float* b2a  = (const float*)d_in[9];
    const float* W2b  = (const float*)d_in[10];
    const float* b2b  = (const float*)d_in[11];
    const float* Wp   = (const float*)d_in[12];
    const float* bp   = (const float*)d_in[13];
    float* out = (float*)d_out;

    int n1 = in_sizes[0];
    int E1 = in_sizes[1] / 2;
    int np = in_sizes[2] / 2;
    int Q  = in_sizes[3] / 2;
    int E2 = in_sizes[4] / 2;

    int mx = (np > n1) ? np : n1;
    int Em = (E1 > E2) ? E1 : E2;

    long long g1t = ((long long)((E1 + 7) / 8)) * 8;   // threads for scatter1
    long long g2t = ((long long)((E2 + 7) / 8)) * 8;   // threads for scatter2

    // Fork: embed (raw xw, no dinv dependency) runs concurrently with the
    // degree pipeline. Streams/events are host-side objects created per call.
    cudaStream_t s1;
    cudaStreamCreateWithFlags(&s1, cudaStreamNonBlocking);
    cudaEvent_t evFork, evJoin;
    cudaEventCreateWithFlags(&evFork, cudaEventDisableTiming);
    cudaEventCreateWithFlags(&evJoin, cudaEventDisableTiming);

    cudaEventRecord(evFork, 0);
    cudaStreamWaitEvent(s1, evFork, 0);
    k_embed<<<(n1 + 127) / 128, 256, 0, s1>>>(x, emb, W1, n1);
    cudaEventRecord(evJoin, s1);

    // degree pipeline on default stream (hidden under embed)
    int* p_cnt1;  int* p_cnt2f;  int* p_cnt2b;
    cudaGetSymbolAddress((void**)&p_cnt1,  g_cnt1);
    cudaGetSymbolAddress((void**)&p_cnt2f, g_cnt2f);
    cudaGetSymbolAddress((void**)&p_cnt2b, g_cnt2b);
    cudaMemsetAsync(p_cnt1,  0, (size_t)n1 * sizeof(int), 0);
    cudaMemsetAsync(p_cnt2f, 0, (size_t)np * sizeof(int), 0);
    cudaMemsetAsync(p_cnt2b, 0, (size_t)np * sizeof(int), 0);
    k_count<<<((Em + 3) / 4 + 255) / 256, 256>>>(e1, e2, E1, E2);
    k_dinv <<<(mx + 255) / 256, 256>>>(n1, np);

    cudaStreamWaitEvent(0, evJoin, 0);                 // join embed branch
    k_scale   <<<(int)(((long long)n1 * 8 + 255) / 256), 256>>>(n1);
    k_scatter1<<<(int)((g1t + 255) / 256), 256>>>(e1, E1);
    k_pair    <<<(int)(((long long)np * 8 + 255) / 256), 256>>>(pos, W2a, b1, W2b, np);
    k_scatter2<<<(int)((g2t + 255) / 256), 256>>>(e2, E2);
    k_final   <<<(int)(((long long)Q  * 8 + 255) / 256), 256>>>(idx, b2a, b2b, Wp, bp, out, Q);
}